// round 10
// baseline (speedup 1.0000x reference)
#include <cuda_runtime.h>
#include <cuda_fp16.h>
#include <cstdint>

// ============================================================
// EdgeUpdate fused MLP via legacy mma.sync (sm_103 non-'a' target).
// R10: split-K warp pairing + register fusion.
//   8 consumer warps in 4 pairs; pair s owns rows 32s..32s+31 of a
//   128-row tile. Within a pair, warp ph computes GEMM1 cols
//   64ph..64ph+63 (B1 traffic = R8's minimum), applies act in regs
//   (C-frag == A-frag), computes the PARTIAL GEMM2 over its K-half,
//   then the pair sums partials via a lane-aligned SMEM exchange.
//   Gather for the next tile sits between GEMM1 and act so LDG
//   latency hides behind compute. 2 consumer warps per SMSP.
// ============================================================

#define XSTR 400   // 192 f16 + pad (400 % 128 == 16 -> ldmatrix conflict-free)
#define HSTR 272   // 128 f16 + pad (272 % 128 == 16)
#define XBUF (128 * XSTR)               // 51200 per X buffer

#define SO_X0  0
#define SO_X1  XBUF                     // 51200
#define SO_W1  (2 * XBUF)               // 102400
#define SO_W2  (SO_W1 + 128 * XSTR)     // 153600
#define SO_SCR (SO_W2 + 64 * HSTR)      // 171008 (4 pairs x 2 x 32 x 144)
#define SO_B1  (SO_SCR + 4 * 2 * 32 * 144)  // 207872
#define SO_B2  (SO_B1 + 512)
#define SMEM_TOTAL (SO_B2 + 256 + 128)  // ~204 KB

#define BARX(id, cnt) \
    asm volatile("bar.sync %0, %1;" :: "r"(id), "r"(cnt) : "memory")

__device__ __forceinline__ uint32_t s2u(const void* p) {
    uint32_t a;
    asm("{ .reg .u64 t; cvta.to.shared.u64 t, %1; cvt.u32.u64 %0, t; }"
        : "=r"(a) : "l"(p));
    return a;
}

__device__ __forceinline__ uint32_t pkh2(float lo, float hi) {
    uint32_t r;
    asm("cvt.rn.f16x2.f32 %0, %1, %2;" : "=r"(r) : "f"(hi), "f"(lo));
    return r;
}

__device__ __forceinline__ void ldm4(uint32_t* r, uint32_t addr) {
    asm volatile("ldmatrix.sync.aligned.m8n8.x4.shared.b16 {%0,%1,%2,%3}, [%4];"
                 : "=r"(r[0]), "=r"(r[1]), "=r"(r[2]), "=r"(r[3]) : "r"(addr));
}

__device__ __forceinline__ void mma16816(float* d, const uint32_t* a,
                                         uint32_t b0, uint32_t b1) {
    asm volatile(
        "mma.sync.aligned.m16n8k16.row.col.f32.f16.f16.f32 "
        "{%0,%1,%2,%3}, {%4,%5,%6,%7}, {%8,%9}, {%0,%1,%2,%3};"
        : "+f"(d[0]), "+f"(d[1]), "+f"(d[2]), "+f"(d[3])
        : "r"(a[0]), "r"(a[1]), "r"(a[2]), "r"(a[3]), "r"(b0), "r"(b1));
}

// shifted softplus: max(x,0) + ln(1+e^{-|x|}) - ln2.
// ln(1+t), t in (0,1], deg-5 polynomial (abs err ~1e-5 << f16 quantization).
__device__ __forceinline__ float ssp(float x) {
    float t = __expf(-fabsf(x));
    float p = fmaf(0.0304544f, t, -0.1315984f);
    p = fmaf(p, t, 0.2852912f);
    p = fmaf(p, t, -0.4902392f);
    p = fmaf(p, t, 0.9992368f);
    return fmaf(p, t, fmaxf(x, 0.0f) - 0.6931472f);
}

// warp w fills rows [16w, 16w+16) of X buffer xb for `tile`
__device__ __forceinline__ void fill16(
    uint32_t xb, long long tile, int w, int g_half, int g_li,
    const int* __restrict__ edges, const float* __restrict__ node_state,
    const float* __restrict__ edge_state, int E) {
#pragma unroll 4
    for (int i2 = 0; i2 < 8; i2++) {
        int row = w * 16 + i2 * 2 + g_half;
        long long e = tile * 128 + row;
        long long ec = (e < E) ? e : (long long)(E - 1);
        int2 np2 = ((const int2*)edges)[ec];
        uint32_t xr = xb + (uint32_t)row * XSTR + (uint32_t)g_li * 8u;
        float4 v0 = ((const float4*)(node_state + (long long)np2.x * 64))[g_li];
        float4 v1 = ((const float4*)(node_state + (long long)np2.y * 64))[g_li];
        float4 v2 = __ldcs((const float4*)(edge_state + ec * 64) + g_li);
        uint32_t a0 = pkh2(v0.x, v0.y), a1 = pkh2(v0.z, v0.w);
        uint32_t c0 = pkh2(v1.x, v1.y), c1 = pkh2(v1.z, v1.w);
        uint32_t d0 = pkh2(v2.x, v2.y), d1 = pkh2(v2.z, v2.w);
        asm volatile("st.shared.v2.b32 [%0], {%1,%2};"
                     :: "r"(xr), "r"(a0), "r"(a1) : "memory");
        asm volatile("st.shared.v2.b32 [%0], {%1,%2};"
                     :: "r"(xr + 128), "r"(c0), "r"(c1) : "memory");
        asm volatile("st.shared.v2.b32 [%0], {%1,%2};"
                     :: "r"(xr + 256), "r"(d0), "r"(d1) : "memory");
    }
}

__global__ void __launch_bounds__(256, 1)
edge_update_kernel(const float* __restrict__ edge_state,
                   const int* __restrict__ edges,
                   const float* __restrict__ node_state,
                   const float* __restrict__ W1, const float* __restrict__ b1,
                   const float* __restrict__ W2, const float* __restrict__ b2,
                   float* __restrict__ out, int E) {
    extern __shared__ __align__(128) char smem[];
    uint32_t sb = s2u(smem);
    int tid = threadIdx.x;
    int lane = tid & 31, w = tid >> 5;

    // ---- one-time: stage weights (f32 -> f16) + biases into SMEM ----
    for (int i = tid; i < 128 * 192; i += 256) {
        int n = i / 192, k = i - n * 192;
        *(half*)(smem + SO_W1 + n * XSTR + k * 2) = __float2half_rn(W1[i]);
    }
    for (int i = tid; i < 64 * 128; i += 256) {
        int n = i >> 7, k = i & 127;
        *(half*)(smem + SO_W2 + n * HSTR + k * 2) = __float2half_rn(W2[i]);
    }
    if (tid < 128) ((float*)(smem + SO_B1))[tid] = b1[tid];
    if (tid < 64)  ((float*)(smem + SO_B2))[tid] = b2[tid];

    const int ntiles = (E + 127) >> 7;
    const int g_half = lane >> 4;
    const int g_li   = lane & 15;

    const int s  = w >> 1;            // pair id 0..3
    const int ph = w & 1;             // column half within pair
    const int m0 = s * 32;            // pair rows
    const int pairbar = 1 + s;        // named barrier per pair

    const int a_r = lane & 15;
    const int a_c = (lane >> 4) << 3;
    const int b_r = ((lane >> 4) << 3) + (lane & 7);
    const int b_c = ((lane >> 3) & 1) << 3;
    const int cr  = lane >> 2;        // C-frag row
    const int cc2 = 2 * (lane & 3);   // C-frag col pair base

    uint32_t aXo[2];
#pragma unroll
    for (int mt = 0; mt < 2; mt++)
        aXo[mt] = (uint32_t)(m0 + mt * 16 + a_r) * XSTR + a_c * 2;
    uint32_t bW1[4];
#pragma unroll
    for (int np = 0; np < 4; np++)
        bW1[np] = sb + SO_W1
                + (uint32_t)(64 * ph + np * 16 + b_r) * XSTR + b_c * 2;
    uint32_t bW2[4];
#pragma unroll
    for (int np = 0; np < 4; np++)
        bW2[np] = sb + SO_W2 + (uint32_t)(np * 16 + b_r) * HSTR + b_c * 2;

    // scratch: region FOR reader r at SO_SCR + s*9216 + r*4608 + lane*144
    char* scr_w = smem + SO_SCR + s * 9216 + (1 - ph) * 4608 + lane * 144;
    char* scr_r = smem + SO_SCR + s * 9216 + ph * 4608 + lane * 144;

    const float* b1s = (const float*)(smem + SO_B1);
    const float* b2s = (const float*)(smem + SO_B2);

    BARX(0, 256);   // weights staged

    // prologue: fill X0 for first tile
    long long t0 = blockIdx.x;
    if (t0 < ntiles)
        fill16(sb + SO_X0, t0, w, g_half, g_li, edges, node_state,
               edge_state, E);

    int it = 0;
    for (long long t = t0; t < ntiles; t += gridDim.x, it++) {
        BARX(0, 256);   // X buf[it&1] ready; prior scratch reads done
        uint32_t xb = sb + ((it & 1) ? SO_X1 : SO_X0);
        uint32_t xo = sb + ((it & 1) ? SO_X0 : SO_X1);

        // ============ GEMM1: 32 rows x 64 cols (half), K=192 ============
        float acc[2][8][4];
#pragma unroll
        for (int mt = 0; mt < 2; mt++)
#pragma unroll
            for (int nt = 0; nt < 8; nt++)
#pragma unroll
                for (int q = 0; q < 4; q++) acc[mt][nt][q] = 0.0f;

#pragma unroll
        for (int k = 0; k < 12; k++) {
            uint32_t A0[4], A1[4], B[4][4];
            ldm4(A0, xb + aXo[0] + k * 32);
            ldm4(A1, xb + aXo[1] + k * 32);
#pragma unroll
            for (int np = 0; np < 4; np++) ldm4(B[np], bW1[np] + k * 32);
#pragma unroll
            for (int np = 0; np < 4; np++) {
#pragma unroll
                for (int h = 0; h < 2; h++) {
                    mma16816(acc[0][np * 2 + h], A0, B[np][2 * h], B[np][2 * h + 1]);
                    mma16816(acc[1][np * 2 + h], A1, B[np][2 * h], B[np][2 * h + 1]);
                }
            }
        }

        // ===== gather next tile into the other buffer (latency overlaps
        //       the act + GEMM2 below) =====
        {
            long long tn = t + gridDim.x;
            if (tn < ntiles)
                fill16(xo, tn, w, g_half, g_li, edges, node_state,
                       edge_state, E);
        }

        // ==== fused act + partial GEMM2 over this warp's K-half ====
        float acc2[2][8][4];
#pragma unroll
        for (int mt = 0; mt < 2; mt++)
#pragma unroll
            for (int nt = 0; nt < 8; nt++)
#pragma unroll
                for (int q = 0; q < 4; q++) acc2[mt][nt][q] = 0.0f;

#pragma unroll
        for (int jj = 0; jj < 4; jj++) {
            int cb = 64 * ph + 16 * jj;
            float2 bl = *(const float2*)(b1s + cb + cc2);
            float2 bh = *(const float2*)(b1s + cb + 8 + cc2);
            uint32_t Af[2][4];
#pragma unroll
            for (int mt = 0; mt < 2; mt++) {
                Af[mt][0] = pkh2(ssp(acc[mt][2 * jj][0] + bl.x),
                                 ssp(acc[mt][2 * jj][1] + bl.y));
                Af[mt][1] = pkh2(ssp(acc[mt][2 * jj][2] + bl.x),
                                 ssp(acc[mt][2 * jj][3] + bl.y));
                Af[mt][2] = pkh2(ssp(acc[mt][2 * jj + 1][0] + bh.x),
                                 ssp(acc[mt][2 * jj + 1][1] + bh.y));
                Af[mt][3] = pkh2(ssp(acc[mt][2 * jj + 1][2] + bh.x),
                                 ssp(acc[mt][2 * jj + 1][3] + bh.y));
            }
            int jg = 4 * ph + jj;   // global k-group of GEMM2
            uint32_t B2[4][4];
#pragma unroll
            for (int np = 0; np < 4; np++) ldm4(B2[np], bW2[np] + jg * 32);
#pragma unroll
            for (int np = 0; np < 4; np++) {
#pragma unroll
                for (int h = 0; h < 2; h++) {
                    mma16816(acc2[0][np * 2 + h], Af[0],
                             B2[np][2 * h], B2[np][2 * h + 1]);
                    mma16816(acc2[1][np * 2 + h], Af[1],
                             B2[np][2 * h], B2[np][2 * h + 1]);
                }
            }
        }

        // ===== pair reduction: exchange the half we don't keep =====
        // ph keeps nt [4ph,4ph+4); stores nt [4(1-ph),4(1-ph)+4) for partner
        {
            const int sbase = (1 - ph) * 4;
#pragma unroll
            for (int mt = 0; mt < 2; mt++)
#pragma unroll
                for (int ntl = 0; ntl < 4; ntl++)
                    *(float4*)(scr_w + (mt * 4 + ntl) * 16) =
                        *(const float4*)(acc2[mt][sbase + ntl]);
        }
        BARX(pairbar, 64);
        {
            const int kbase = ph * 4;
#pragma unroll
            for (int mt = 0; mt < 2; mt++)
#pragma unroll
                for (int ntl = 0; ntl < 4; ntl++) {
                    float4 pv = *(const float4*)(scr_r + (mt * 4 + ntl) * 16);
                    acc2[mt][kbase + ntl][0] += pv.x;
                    acc2[mt][kbase + ntl][1] += pv.y;
                    acc2[mt][kbase + ntl][2] += pv.z;
                    acc2[mt][kbase + ntl][3] += pv.w;
                }
        }

        // ===== epilogue: out = D2 + b2 for our 32-col half (streaming) =====
        {
            long long rb = t * 128 + m0 + cr;
            const int kbase = ph * 4;
#pragma unroll
            for (int mt = 0; mt < 2; mt++) {
                long long r0e = rb + mt * 16;
#pragma unroll
                for (int ntl = 0; ntl < 4; ntl++) {
                    int c = ph * 32 + ntl * 8 + cc2;
                    float2 bb = *(const float2*)(b2s + c);
                    if (r0e < E) {
                        float2 v;
                        v.x = acc2[mt][kbase + ntl][0] + bb.x;
                        v.y = acc2[mt][kbase + ntl][1] + bb.y;
                        __stcs((float2*)(out + r0e * 64 + c), v);
                    }
                    if (r0e + 8 < E) {
                        float2 v;
                        v.x = acc2[mt][kbase + ntl][2] + bb.x;
                        v.y = acc2[mt][kbase + ntl][3] + bb.y;
                        __stcs((float2*)(out + (r0e + 8) * 64 + c), v);
                    }
                }
            }
        }
    }
}

extern "C" void kernel_launch(void* const* d_in, const int* in_sizes, int n_in,
                              void* d_out, int out_size) {
    const float* edge_state = (const float*)d_in[0];
    const int*   edges      = (const int*)d_in[1];
    const float* node_state = (const float*)d_in[2];
    const float* W1         = (const float*)d_in[3];
    const float* b1         = (const float*)d_in[4];
    const float* W2         = (const float*)d_in[5];
    const float* b2         = (const float*)d_in[6];
    float*       out        = (float*)d_out;
    int E = in_sizes[0] / 64;

    cudaFuncSetAttribute(edge_update_kernel,
                         cudaFuncAttributeMaxDynamicSharedMemorySize, SMEM_TOTAL);
    edge_update_kernel<<<148, 256, SMEM_TOTAL>>>(edge_state, edges, node_state,
                                                 W1, b1, W2, b2, out, E);
}

// round 11
// speedup vs baseline: 1.2763x; 1.2763x over previous
#include <cuda_runtime.h>
#include <cuda_fp16.h>
#include <cstdint>

// ============================================================
// EdgeUpdate fused MLP via legacy mma.sync (sm_103 non-'a' target).
// R11 = R5 (best: 2 CTAs/SM, 64-row tiles, cross-CTA phase overlap)
//       + polynomial shifted-softplus (1 MUFU/elem instead of 2;
//         deg-5 ln(1+t) on the idle FMA pipe).
// Everything else identical to the 295us baseline.
// ============================================================

#define XSTR 400   // 192 f16 + 16B pad
#define HSTR 272   // 128 f16 + 16B pad

#define SO_X   0                       // 64 x XSTR  = 25600
#define SO_W1  (64 * XSTR)             // 128 x XSTR = 51200
#define SO_W2  (SO_W1 + 128 * XSTR)    // 64 x HSTR  = 17408
#define SO_H   (SO_W2 + 64 * HSTR)     // 64 x HSTR  = 17408
#define SO_B1  (SO_H + 64 * HSTR)
#define SO_B2  (SO_B1 + 512)
#define SMEM_TOTAL (SO_B2 + 256 + 128) // 112512 B -> 2 CTAs/SM

__device__ __forceinline__ uint32_t s2u(const void* p) {
    uint32_t a;
    asm("{ .reg .u64 t; cvta.to.shared.u64 t, %1; cvt.u32.u64 %0, t; }"
        : "=r"(a) : "l"(p));
    return a;
}

__device__ __forceinline__ uint32_t pkh2(float lo, float hi) {
    uint32_t r;
    asm("cvt.rn.f16x2.f32 %0, %1, %2;" : "=r"(r) : "f"(hi), "f"(lo));
    return r;
}

__device__ __forceinline__ void ldm4(uint32_t* r, uint32_t addr) {
    asm volatile("ldmatrix.sync.aligned.m8n8.x4.shared.b16 {%0,%1,%2,%3}, [%4];"
                 : "=r"(r[0]), "=r"(r[1]), "=r"(r[2]), "=r"(r[3]) : "r"(addr));
}

__device__ __forceinline__ void mma16816(float* d, const uint32_t* a,
                                         uint32_t b0, uint32_t b1) {
    asm volatile(
        "mma.sync.aligned.m16n8k16.row.col.f32.f16.f16.f32 "
        "{%0,%1,%2,%3}, {%4,%5,%6,%7}, {%8,%9}, {%0,%1,%2,%3};"
        : "+f"(d[0]), "+f"(d[1]), "+f"(d[2]), "+f"(d[3])
        : "r"(a[0]), "r"(a[1]), "r"(a[2]), "r"(a[3]), "r"(b0), "r"(b1));
}

// shifted softplus: max(x,0) + ln(1+e^{-|x|}) - ln2.
// ln(1+t), t in (0,1], deg-5 polynomial (abs err ~1e-5, << f16 quantization
// applied to H). One MUFU (EX2) per element; the poly rides the FMA pipe.
__device__ __forceinline__ float ssp(float x) {
    float t = __expf(-fabsf(x));
    float p = fmaf(0.0304544f, t, -0.1315984f);
    p = fmaf(p, t, 0.2852912f);
    p = fmaf(p, t, -0.4902392f);
    p = fmaf(p, t, 0.9992368f);
    return fmaf(p, t, fmaxf(x, 0.0f) - 0.6931472f);
}

__global__ void __launch_bounds__(256, 2)
edge_update_kernel(const float* __restrict__ edge_state,
                   const int* __restrict__ edges,
                   const float* __restrict__ node_state,
                   const float* __restrict__ W1, const float* __restrict__ b1,
                   const float* __restrict__ W2, const float* __restrict__ b2,
                   float* __restrict__ out, int E) {
    extern __shared__ __align__(128) char smem[];
    uint32_t sb = s2u(smem);
    int tid = threadIdx.x;
    int lane = tid & 31, w = tid >> 5;

    // ---- one-time: stage weights (f32 -> f16) + biases into SMEM ----
    for (int i = tid; i < 128 * 192; i += 256) {
        int n = i / 192, k = i - n * 192;
        *(half*)(smem + SO_W1 + n * XSTR + k * 2) = __float2half_rn(W1[i]);
    }
    for (int i = tid; i < 64 * 128; i += 256) {
        int n = i >> 7, k = i & 127;
        *(half*)(smem + SO_W2 + n * HSTR + k * 2) = __float2half_rn(W2[i]);
    }
    if (tid < 128) ((float*)(smem + SO_B1))[tid] = b1[tid];
    if (tid < 64)  ((float*)(smem + SO_B2))[tid] = b2[tid];
    __syncthreads();

    // warp tiling: 2 m-groups x 4 n-groups over the 64x128 GEMM1 tile
    const int m0  = (w & 1) * 32;    // 32 rows per warp
    const int n0  = (w >> 1) * 32;   // GEMM1: 32 cols per warp
    const int n02 = (w >> 1) * 16;   // GEMM2: 16 cols per warp

    // per-lane bias pairs (loop-invariant)
    float2 b1v[4], b2v[2];
    {
        const float* b1s = (const float*)(smem + SO_B1);
        const float* b2s = (const float*)(smem + SO_B2);
        int cb = 2 * (lane & 3);
#pragma unroll
        for (int nt = 0; nt < 4; nt++) {
            int c = n0 + nt * 8 + cb;
            b1v[nt] = make_float2(b1s[c], b1s[c + 1]);
        }
#pragma unroll
        for (int nt = 0; nt < 2; nt++) {
            int c = n02 + nt * 8 + cb;
            b2v[nt] = make_float2(b2s[c], b2s[c + 1]);
        }
    }

    // ldmatrix per-lane address components
    const int a_r = lane & 15;                       // A: row within 16
    const int a_c = (lane >> 4) << 3;                // A: k offset 0/8
    const int b_r = ((lane >> 4) << 3) + (lane & 7); // B: n-row within 16
    const int b_c = ((lane >> 3) & 1) << 3;          // B: k offset 0/8

    uint32_t aX[2], aH[2], bW1[2], bW2;
#pragma unroll
    for (int mt = 0; mt < 2; mt++) {
        aX[mt] = sb + SO_X + (uint32_t)(m0 + mt * 16 + a_r) * XSTR + a_c * 2;
        aH[mt] = sb + SO_H + (uint32_t)(m0 + mt * 16 + a_r) * HSTR + a_c * 2;
    }
#pragma unroll
    for (int np = 0; np < 2; np++)
        bW1[np] = sb + SO_W1 + (uint32_t)(n0 + np * 16 + b_r) * XSTR + b_c * 2;
    bW2 = sb + SO_W2 + (uint32_t)(n02 + b_r) * HSTR + b_c * 2;

    const int act_r = lane >> 2;
    const int act_c = 2 * (lane & 3);

    // gather lane mapping: half-warp per row, lane li owns float4 #li
    const int g_half = lane >> 4;
    const int g_li   = lane & 15;

    int ntiles = (E + 63) >> 6;
    for (int t = blockIdx.x; t < ntiles; t += gridDim.x) {
        // ========== coalesced gather -> f16 X tile (64 rows) ==========
        // warp w handles rows [8w, 8w+8); per iter 2 rows (one per half-warp)
#pragma unroll
        for (int it = 0; it < 4; it++) {
            int row = w * 8 + it * 2 + g_half;
            long long e = (long long)t * 64 + row;
            long long ec = (e < E) ? e : (long long)(E - 1);
            int2 np2 = ((const int2*)edges)[ec];
            uint32_t xr = sb + SO_X + (uint32_t)row * XSTR + (uint32_t)g_li * 8u;
            float4 v0 = ((const float4*)(node_state + (long long)np2.x * 64))[g_li];
            float4 v1 = ((const float4*)(node_state + (long long)np2.y * 64))[g_li];
            float4 v2 = __ldcs((const float4*)(edge_state + ec * 64) + g_li);
            uint32_t a0 = pkh2(v0.x, v0.y), a1 = pkh2(v0.z, v0.w);
            uint32_t c0 = pkh2(v1.x, v1.y), c1 = pkh2(v1.z, v1.w);
            uint32_t d0 = pkh2(v2.x, v2.y), d1 = pkh2(v2.z, v2.w);
            asm volatile("st.shared.v2.b32 [%0], {%1,%2};"
                         :: "r"(xr), "r"(a0), "r"(a1) : "memory");
            asm volatile("st.shared.v2.b32 [%0], {%1,%2};"
                         :: "r"(xr + 128), "r"(c0), "r"(c1) : "memory");
            asm volatile("st.shared.v2.b32 [%0], {%1,%2};"
                         :: "r"(xr + 256), "r"(d0), "r"(d1) : "memory");
        }
        __syncthreads();

        // ================= GEMM1: 32x32, K=192 =================
        float acc[2][4][4];
#pragma unroll
        for (int mt = 0; mt < 2; mt++)
#pragma unroll
            for (int nt = 0; nt < 4; nt++)
#pragma unroll
                for (int q = 0; q < 4; q++) acc[mt][nt][q] = 0.0f;

#pragma unroll
        for (int k = 0; k < 12; k++) {
            uint32_t A0[4], A1[4], B[2][4];
            ldm4(A0, aX[0] + k * 32);
            ldm4(A1, aX[1] + k * 32);
            ldm4(B[0], bW1[0] + k * 32);
            ldm4(B[1], bW1[1] + k * 32);
#pragma unroll
            for (int np = 0; np < 2; np++) {
#pragma unroll
                for (int h = 0; h < 2; h++) {
                    mma16816(acc[0][np * 2 + h], A0, B[np][2 * h], B[np][2 * h + 1]);
                    mma16816(acc[1][np * 2 + h], A1, B[np][2 * h], B[np][2 * h + 1]);
                }
            }
        }

        // ============ activation -> f16 H tile ============
#pragma unroll
        for (int mt = 0; mt < 2; mt++) {
            uint32_t ha = sb + SO_H
                        + (uint32_t)(m0 + mt * 16 + act_r) * HSTR
                        + (uint32_t)(n0 + act_c) * 2;
#pragma unroll
            for (int nt = 0; nt < 4; nt++) {
                float x0 = acc[mt][nt][0] + b1v[nt].x;
                float x1 = acc[mt][nt][1] + b1v[nt].y;
                float x2 = acc[mt][nt][2] + b1v[nt].x;
                float x3 = acc[mt][nt][3] + b1v[nt].y;
                uint32_t h01 = pkh2(ssp(x0), ssp(x1));
                uint32_t h23 = pkh2(ssp(x2), ssp(x3));
                asm volatile("st.shared.b32 [%0], %1;"
                             :: "r"(ha + nt * 16), "r"(h01) : "memory");
                asm volatile("st.shared.b32 [%0], %1;"
                             :: "r"(ha + nt * 16 + 8 * HSTR), "r"(h23) : "memory");
            }
        }
        __syncthreads();

        // ================= GEMM2: 32x16, K=128 =================
        float acc2[2][2][4];
#pragma unroll
        for (int mt = 0; mt < 2; mt++)
#pragma unroll
            for (int nt = 0; nt < 2; nt++)
#pragma unroll
                for (int q = 0; q < 4; q++) acc2[mt][nt][q] = 0.0f;

#pragma unroll
        for (int k = 0; k < 8; k++) {
            uint32_t A0[4], A1[4], B[4];
            ldm4(A0, aH[0] + k * 32);
            ldm4(A1, aH[1] + k * 32);
            ldm4(B, bW2 + k * 32);
#pragma unroll
            for (int h = 0; h < 2; h++) {
                mma16816(acc2[0][h], A0, B[2 * h], B[2 * h + 1]);
                mma16816(acc2[1][h], A1, B[2 * h], B[2 * h + 1]);
            }
        }

        // ================= epilogue: out = D2 + b2 (streaming) ==========
        // no trailing sync: next gather's X writes are ordered against this
        // tile's GEMM1 reads by the act-sync; GEMM2 touches only H/W2, and
        // the next gather-sync orders H rewrites after all GEMM2 reads.
        {
            long long ebase = (long long)t * 64 + m0 + act_r;
#pragma unroll
            for (int mt = 0; mt < 2; mt++) {
                long long r0e = ebase + mt * 16;
#pragma unroll
                for (int nt = 0; nt < 2; nt++) {
                    int c = n02 + nt * 8 + act_c;
                    if (r0e < E) {
                        float2 v;
                        v.x = acc2[mt][nt][0] + b2v[nt].x;
                        v.y = acc2[mt][nt][1] + b2v[nt].y;
                        __stcs((float2*)(out + r0e * 64 + c), v);
                    }
                    if (r0e + 8 < E) {
                        float2 v;
                        v.x = acc2[mt][nt][2] + b2v[nt].x;
                        v.y = acc2[mt][nt][3] + b2v[nt].y;
                        __stcs((float2*)(out + (r0e + 8) * 64 + c), v);
                    }
                }
            }
        }
    }
}

extern "C" void kernel_launch(void* const* d_in, const int* in_sizes, int n_in,
                              void* d_out, int out_size) {
    const float* edge_state = (const float*)d_in[0];
    const int*   edges      = (const int*)d_in[1];
    const float* node_state = (const float*)d_in[2];
    const float* W1         = (const float*)d_in[3];
    const float* b1         = (const float*)d_in[4];
    const float* W2         = (const float*)d_in[5];
    const float* b2         = (const float*)d_in[6];
    float*       out        = (float*)d_out;
    int E = in_sizes[0] / 64;

    cudaFuncSetAttribute(edge_update_kernel,
                         cudaFuncAttributeMaxDynamicSharedMemorySize, SMEM_TOTAL);
    edge_update_kernel<<<296, 256, SMEM_TOTAL>>>(edge_state, edges, node_state,
                                                 W1, b1, W2, b2, out, E);
}

// round 12
// speedup vs baseline: 1.3891x; 1.0884x over previous
#include <cuda_runtime.h>
#include <cuda_fp16.h>
#include <cstdint>

// ============================================================
// EdgeUpdate fused MLP via legacy mma.sync (sm_103 non-'a' target).
// R12 = R5 skeleton (2 CTAs/SM, 64-row tiles, cross-CTA overlap)
//   + W1 B-fragments PERSISTENT IN REGISTERS (96/thread), built
//     once directly from global W1 — eliminates all GEMM1
//     B-ldmatrix traffic and the W1 SMEM tile entirely.
//   128-thread CTAs (4 warps, 1m x 4n: warp = 64 rows x 32 cols),
//   reg budget 256/thread at 2 CTAs/SM. W2 stays in SMEM.
//   __log2f softplus (poly A/B in R11 measured slower).
// ============================================================

#define XSTR 400   // 192 f16 + 16B pad
#define HSTR 272   // 128 f16 + 16B pad

#define SO_X   0                       // 64 x XSTR = 25600
#define SO_W2  25600                   // 64 x HSTR = 17408
#define SO_H   (SO_W2 + 64 * HSTR)     // 43008
#define SO_B1  (SO_H + 64 * HSTR)      // 60416
#define SO_B2  (SO_B1 + 512)           // 60928
#define SMEM_TOTAL (SO_B2 + 256 + 128) // 61312 B -> 2 CTAs/SM easily

__device__ __forceinline__ uint32_t s2u(const void* p) {
    uint32_t a;
    asm("{ .reg .u64 t; cvta.to.shared.u64 t, %1; cvt.u32.u64 %0, t; }"
        : "=r"(a) : "l"(p));
    return a;
}

__device__ __forceinline__ uint32_t pkh2(float lo, float hi) {
    uint32_t r;
    asm("cvt.rn.f16x2.f32 %0, %1, %2;" : "=r"(r) : "f"(hi), "f"(lo));
    return r;
}

__device__ __forceinline__ void ldm4(uint32_t* r, uint32_t addr) {
    asm volatile("ldmatrix.sync.aligned.m8n8.x4.shared.b16 {%0,%1,%2,%3}, [%4];"
                 : "=r"(r[0]), "=r"(r[1]), "=r"(r[2]), "=r"(r[3]) : "r"(addr));
}

__device__ __forceinline__ void mma16816(float* d, const uint32_t* a,
                                         uint32_t b0, uint32_t b1) {
    asm volatile(
        "mma.sync.aligned.m16n8k16.row.col.f32.f16.f16.f32 "
        "{%0,%1,%2,%3}, {%4,%5,%6,%7}, {%8,%9}, {%0,%1,%2,%3};"
        : "+f"(d[0]), "+f"(d[1]), "+f"(d[2]), "+f"(d[3])
        : "r"(a[0]), "r"(a[1]), "r"(a[2]), "r"(a[3]), "r"(b0), "r"(b1));
}

// shifted softplus: softplus(x) - ln2 = max(x,0) + ln(1+e^{-|x|}) - ln2
__device__ __forceinline__ float ssp(float x) {
    float e = __expf(-fabsf(x));
    float l = __log2f(1.0f + e);
    return fmaxf(x, 0.0f) + 0.6931471805599453f * (l - 1.0f);
}

__global__ void __launch_bounds__(128, 2)
edge_update_kernel(const float* __restrict__ edge_state,
                   const int* __restrict__ edges,
                   const float* __restrict__ node_state,
                   const float* __restrict__ W1, const float* __restrict__ b1,
                   const float* __restrict__ W2, const float* __restrict__ b2,
                   float* __restrict__ out, int E) {
    extern __shared__ __align__(128) char smem[];
    uint32_t sb = s2u(smem);
    int tid = threadIdx.x;
    int lane = tid & 31, w = tid >> 5;

    // ---- one-time: stage W2 (f32 -> f16) + biases into SMEM ----
    for (int i = tid; i < 64 * 128; i += 128) {
        int n = i >> 7, k = i & 127;
        *(half*)(smem + SO_W2 + n * HSTR + k * 2) = __float2half_rn(W2[i]);
    }
    ((float*)(smem + SO_B1))[tid] = b1[tid];
    if (tid < 64) ((float*)(smem + SO_B2))[tid] = b2[tid];

    // warp tiling: 1m x 4n over 64x128 (GEMM1); GEMM2 n = 16/warp
    const int n0  = w * 32;
    const int n02 = w * 16;

    // ---- one-time: build persistent W1 B-fragments from global ----
    // m16n8k16 B-frag per-lane mapping: b0 = (n = base + lane/4,
    // k = 2*(lane&3) + {0,1}); b1 = k+8; (regs 2,3 = n+8 subtile).
    const int fl = lane >> 2;
    const int fk = 2 * (lane & 3);
    uint32_t Bf[12][2][4];
#pragma unroll
    for (int k = 0; k < 12; k++) {
#pragma unroll
        for (int g = 0; g < 2; g++) {
            const float* p0 = W1 + (n0 + 16 * g + fl) * 192 + 16 * k + fk;
            const float* p1 = p0 + 8 * 192;
            Bf[k][g][0] = pkh2(p0[0], p0[1]);
            Bf[k][g][1] = pkh2(p0[8], p0[9]);
            Bf[k][g][2] = pkh2(p1[0], p1[1]);
            Bf[k][g][3] = pkh2(p1[8], p1[9]);
        }
    }
    __syncthreads();

    // per-lane bias pairs (loop-invariant)
    float2 b1v[4], b2v[2];
    {
        const float* b1s = (const float*)(smem + SO_B1);
        const float* b2s = (const float*)(smem + SO_B2);
        int cb = 2 * (lane & 3);
#pragma unroll
        for (int nt = 0; nt < 4; nt++)
            b1v[nt] = *(const float2*)(b1s + n0 + nt * 8 + cb);
#pragma unroll
        for (int h = 0; h < 2; h++)
            b2v[h] = *(const float2*)(b2s + n02 + h * 8 + cb);
    }

    // ldmatrix per-lane address components
    const int a_r = lane & 15;
    const int a_c = (lane >> 4) << 3;
    const int b_r = ((lane >> 4) << 3) + (lane & 7);
    const int b_c = ((lane >> 3) & 1) << 3;

    uint32_t aX[4], aH[4];
#pragma unroll
    for (int mt = 0; mt < 4; mt++) {
        aX[mt] = sb + SO_X + (uint32_t)(mt * 16 + a_r) * XSTR + a_c * 2;
        aH[mt] = sb + SO_H + (uint32_t)(mt * 16 + a_r) * HSTR + a_c * 2;
    }
    const uint32_t bW2 = sb + SO_W2 + (uint32_t)(n02 + b_r) * HSTR + b_c * 2;

    const int act_r = lane >> 2;
    const int act_c = 2 * (lane & 3);

    // gather lane mapping: half-warp per row, lane li owns float4 #li
    const int g_half = lane >> 4;
    const int g_li   = lane & 15;

    int ntiles = (E + 63) >> 6;
    for (int t = blockIdx.x; t < ntiles; t += gridDim.x) {
        // ========== coalesced gather -> f16 X tile (64 rows) ==========
        // warp w handles rows [16w, 16w+16); 2 rows per iter
#pragma unroll
        for (int it = 0; it < 8; it++) {
            int row = w * 16 + it * 2 + g_half;
            long long e = (long long)t * 64 + row;
            long long ec = (e < E) ? e : (long long)(E - 1);
            int2 np2 = ((const int2*)edges)[ec];
            uint32_t xr = sb + SO_X + (uint32_t)row * XSTR + (uint32_t)g_li * 8u;
            float4 v0 = ((const float4*)(node_state + (long long)np2.x * 64))[g_li];
            float4 v1 = ((const float4*)(node_state + (long long)np2.y * 64))[g_li];
            float4 v2 = __ldcs((const float4*)(edge_state + ec * 64) + g_li);
            uint32_t a0 = pkh2(v0.x, v0.y), a1 = pkh2(v0.z, v0.w);
            uint32_t c0 = pkh2(v1.x, v1.y), c1 = pkh2(v1.z, v1.w);
            uint32_t d0 = pkh2(v2.x, v2.y), d1 = pkh2(v2.z, v2.w);
            asm volatile("st.shared.v2.b32 [%0], {%1,%2};"
                         :: "r"(xr), "r"(a0), "r"(a1) : "memory");
            asm volatile("st.shared.v2.b32 [%0], {%1,%2};"
                         :: "r"(xr + 128), "r"(c0), "r"(c1) : "memory");
            asm volatile("st.shared.v2.b32 [%0], {%1,%2};"
                         :: "r"(xr + 256), "r"(d0), "r"(d1) : "memory");
        }
        __syncthreads();

        // ====== GEMM1: 64 rows x 32 cols per warp, K=192, B in regs ======
        float acc[4][4][4];
#pragma unroll
        for (int mt = 0; mt < 4; mt++)
#pragma unroll
            for (int nt = 0; nt < 4; nt++)
#pragma unroll
                for (int q = 0; q < 4; q++) acc[mt][nt][q] = 0.0f;

#pragma unroll
        for (int k = 0; k < 12; k++) {
            uint32_t Am[4][4];
#pragma unroll
            for (int mt = 0; mt < 4; mt++) ldm4(Am[mt], aX[mt] + k * 32);
#pragma unroll
            for (int g = 0; g < 2; g++) {
#pragma unroll
                for (int mt = 0; mt < 4; mt++) {
                    mma16816(acc[mt][2 * g],     Am[mt], Bf[k][g][0], Bf[k][g][1]);
                    mma16816(acc[mt][2 * g + 1], Am[mt], Bf[k][g][2], Bf[k][g][3]);
                }
            }
        }

        // ============ activation -> f16 H tile ============
#pragma unroll
        for (int mt = 0; mt < 4; mt++) {
            uint32_t ha = sb + SO_H
                        + (uint32_t)(mt * 16 + act_r) * HSTR
                        + (uint32_t)(n0 + act_c) * 2;
#pragma unroll
            for (int nt = 0; nt < 4; nt++) {
                float x0 = acc[mt][nt][0] + b1v[nt].x;
                float x1 = acc[mt][nt][1] + b1v[nt].y;
                float x2 = acc[mt][nt][2] + b1v[nt].x;
                float x3 = acc[mt][nt][3] + b1v[nt].y;
                uint32_t h01 = pkh2(ssp(x0), ssp(x1));
                uint32_t h23 = pkh2(ssp(x2), ssp(x3));
                asm volatile("st.shared.b32 [%0], %1;"
                             :: "r"(ha + nt * 16), "r"(h01) : "memory");
                asm volatile("st.shared.b32 [%0], %1;"
                             :: "r"(ha + nt * 16 + 8 * HSTR), "r"(h23) : "memory");
            }
        }
        __syncthreads();

        // ============ GEMM2: 64 rows x 16 cols per warp, K=128 ============
        float acc2[4][2][4];
#pragma unroll
        for (int mt = 0; mt < 4; mt++)
#pragma unroll
            for (int h = 0; h < 2; h++)
#pragma unroll
                for (int q = 0; q < 4; q++) acc2[mt][h][q] = 0.0f;

#pragma unroll
        for (int k = 0; k < 8; k++) {
            uint32_t Am[4][4], B2[4];
#pragma unroll
            for (int mt = 0; mt < 4; mt++) ldm4(Am[mt], aH[mt] + k * 32);
            ldm4(B2, bW2 + k * 32);
#pragma unroll
            for (int mt = 0; mt < 4; mt++) {
                mma16816(acc2[mt][0], Am[mt], B2[0], B2[1]);
                mma16816(acc2[mt][1], Am[mt], B2[2], B2[3]);
            }
        }

        // ============ epilogue: out = D2 + b2 (streaming) ============
        // no trailing sync: next gather writes X only (ordered by act-sync);
        // H rewrites are ordered after GEMM2 reads by the next gather-sync.
        {
            long long ebase = (long long)t * 64 + act_r;
#pragma unroll
            for (int mt = 0; mt < 4; mt++) {
                long long r0e = ebase + mt * 16;
#pragma unroll
                for (int h = 0; h < 2; h++) {
                    int c = n02 + h * 8 + act_c;
                    if (r0e < E) {
                        float2 v;
                        v.x = acc2[mt][h][0] + b2v[h].x;
                        v.y = acc2[mt][h][1] + b2v[h].y;
                        __stcs((float2*)(out + r0e * 64 + c), v);
                    }
                    if (r0e + 8 < E) {
                        float2 v;
                        v.x = acc2[mt][h][2] + b2v[h].x;
                        v.y = acc2[mt][h][3] + b2v[h].y;
                        __stcs((float2*)(out + (r0e + 8) * 64 + c), v);
                    }
                }
            }
        }
    }
}

extern "C" void kernel_launch(void* const* d_in, const int* in_sizes, int n_in,
                              void* d_out, int out_size) {
    const float* edge_state = (const float*)d_in[0];
    const int*   edges      = (const int*)d_in[1];
    const float* node_state = (const float*)d_in[2];
    const float* W1         = (const float*)d_in[3];
    const float* b1         = (const float*)d_in[4];
    const float* W2         = (const float*)d_in[5];
    const float* b2         = (const float*)d_in[6];
    float*       out        = (float*)d_out;
    int E = in_sizes[0] / 64;

    cudaFuncSetAttribute(edge_update_kernel,
                         cudaFuncAttributeMaxDynamicSharedMemorySize, SMEM_TOTAL);
    edge_update_kernel<<<296, 128, SMEM_TOTAL>>>(edge_state, edges, node_state,
                                                 W1, b1, W2, b2, out, E);
}